// round 1
// baseline (speedup 1.0000x reference)
#include <cuda_runtime.h>
#include <cuda_bf16.h>
#include <cstdint>

#define N_NODES 50000
#define N_EDGES 300000
#define MAXF    256

// ---------------- scratch (device globals; no allocation allowed) ----------
__device__ float g_support[(size_t)N_NODES * MAXF];
__device__ float g_agg    [(size_t)N_NODES * MAXF];
__device__ float g_h      [(size_t)N_NODES * MAXF];
__device__ float g_l3     [(size_t)N_NODES * MAXF];
__device__ float g_l4     [(size_t)N_NODES * MAXF];

// ---------------- SGEMM: C[M,N] = A[M,K] @ B[K,N] --------------------------
// BM=128, BN=64, BK=16, thread tile 8x4, 256 threads/block.
// K,N are multiples of 64 here, so only M needs guarding.
__global__ __launch_bounds__(256) void sgemm_kernel(
    const float* __restrict__ A, const float* __restrict__ B,
    float* __restrict__ C, int M, int K, int N)
{
    const int BM = 128, BN = 64, BK = 16, TM = 8, TN = 4;
    __shared__ float As[BK][BM];
    __shared__ float Bs[BK][BN];

    int tid = threadIdx.x;
    int block_row = blockIdx.x * BM;
    int block_col = blockIdx.y * BN;

    int tx = tid % (BN / TN);   // 0..15  (N dir)
    int ty = tid / (BN / TN);   // 0..15  (M dir)

    float acc[TM][TN];
    #pragma unroll
    for (int i = 0; i < TM; i++)
        #pragma unroll
        for (int j = 0; j < TN; j++) acc[i][j] = 0.f;

    for (int k0 = 0; k0 < K; k0 += BK) {
        // Load A tile (BM x BK) as float4 along K, store transposed.
        #pragma unroll
        for (int p = 0; p < 2; p++) {
            int r  = (tid >> 2) + p * 64;     // row within tile
            int kk = (tid & 3) * 4;           // k within tile
            int grow = block_row + r;
            float4 v = make_float4(0.f, 0.f, 0.f, 0.f);
            if (grow < M)
                v = *(const float4*)&A[(size_t)grow * K + k0 + kk];
            As[kk + 0][r] = v.x;
            As[kk + 1][r] = v.y;
            As[kk + 2][r] = v.z;
            As[kk + 3][r] = v.w;
        }
        // Load B tile (BK x BN), one float4 per thread.
        {
            int r = tid >> 4;                  // 0..15
            int c = (tid & 15) * 4;            // 0..60
            float4 v = *(const float4*)&B[(size_t)(k0 + r) * N + block_col + c];
            *(float4*)&Bs[r][c] = v;
        }
        __syncthreads();

        #pragma unroll
        for (int k = 0; k < BK; k++) {
            float a[TM], bv[TN];
            #pragma unroll
            for (int i = 0; i < TM; i++) a[i] = As[k][ty * TM + i];
            #pragma unroll
            for (int j = 0; j < TN; j++) bv[j] = Bs[k][tx * TN + j];
            #pragma unroll
            for (int i = 0; i < TM; i++)
                #pragma unroll
                for (int j = 0; j < TN; j++)
                    acc[i][j] += a[i] * bv[j];
        }
        __syncthreads();
    }

    #pragma unroll
    for (int i = 0; i < TM; i++) {
        int grow = block_row + ty * TM + i;
        if (grow < M) {
            float4 v = make_float4(acc[i][0], acc[i][1], acc[i][2], acc[i][3]);
            *(float4*)&C[(size_t)grow * N + block_col + tx * TN] = v;
        }
    }
}

// ---------------- agg[i*dout+j] = bias[j] ----------------------------------
__global__ void init_bias_kernel(float4* __restrict__ agg,
                                 const float4* __restrict__ b4,
                                 int total4, int mask4)   // mask4 = dout/4 - 1
{
    int i = blockIdx.x * blockDim.x + threadIdx.x;
    if (i < total4) agg[i] = b4[i & mask4];
}

// ---------------- scatter: agg[dst] += support[src] * w --------------------
// One thread per (edge, 4-feature chunk). 64 consecutive threads share an
// edge -> fully coalesced gather and contiguous vector atomics.
__global__ void scatter_kernel(const float4* __restrict__ support,
                               const int*   __restrict__ src,
                               const int*   __restrict__ dst,
                               const float* __restrict__ w,
                               float4* __restrict__ agg,
                               int E, int nchunk)          // nchunk = dout/4
{
    int idx = blockIdx.x * blockDim.x + threadIdx.x;
    int e = idx / nchunk;
    int c = idx - e * nchunk;
    if (e >= E) return;
    int   s  = __ldg(&src[e]);
    int   d  = __ldg(&dst[e]);
    float wt = __ldg(&w[e]);
    float4 v = __ldg(&support[(size_t)s * nchunk + c]);
    float4 m = make_float4(v.x * wt, v.y * wt, v.z * wt, v.w * wt);
#if __CUDA_ARCH__ >= 900
    atomicAdd(&agg[(size_t)d * nchunk + c], m);
#else
    float* o = (float*)&agg[(size_t)d * nchunk + c];
    atomicAdd(o + 0, m.x); atomicAdd(o + 1, m.y);
    atomicAdd(o + 2, m.z); atomicAdd(o + 3, m.w);
#endif
}

// ---------------- epilogue: relu (+ optional residual sums) ----------------
// r = relu(agg). out0 (if non-null) <- r. out_sum (if non-null) <- r + add1
// (+ add2 if non-null).
__global__ void epilogue_kernel(const float4* __restrict__ agg,
                                float4* __restrict__ out0,
                                float4* __restrict__ out_sum,
                                const float4* __restrict__ add1,
                                const float4* __restrict__ add2,
                                int total4)
{
    int i = blockIdx.x * blockDim.x + threadIdx.x;
    if (i >= total4) return;
    float4 a = agg[i];
    float4 r = make_float4(fmaxf(a.x, 0.f), fmaxf(a.y, 0.f),
                           fmaxf(a.z, 0.f), fmaxf(a.w, 0.f));
    if (out0) out0[i] = r;
    if (out_sum) {
        float4 s1 = add1[i];
        float4 s = make_float4(r.x + s1.x, r.y + s1.y, r.z + s1.z, r.w + s1.w);
        if (add2) {
            float4 s2 = add2[i];
            s.x += s2.x; s.y += s2.y; s.z += s2.z; s.w += s2.w;
        }
        out_sum[i] = s;
    }
}

// ---------------------------------------------------------------------------
extern "C" void kernel_launch(void* const* d_in, const int* in_sizes, int n_in,
                              void* d_out, int out_size)
{
    const float* x    = (const float*)d_in[0];
    const int*   esrc = (const int*)  d_in[1];
    const int*   edst = (const int*)  d_in[2];
    const float* ew   = (const float*)d_in[3];
    const float* W[6];
    const float* b[6];
    for (int i = 0; i < 6; i++) {
        W[i] = (const float*)d_in[4 + 2 * i];
        b[i] = (const float*)d_in[5 + 2 * i];
    }

    float *support, *agg, *h, *l3, *l4;
    cudaGetSymbolAddress((void**)&support, g_support);
    cudaGetSymbolAddress((void**)&agg,     g_agg);
    cudaGetSymbolAddress((void**)&h,       g_h);
    cudaGetSymbolAddress((void**)&l3,      g_l3);
    cudaGetSymbolAddress((void**)&l4,      g_l4);

    auto gconv = [&](const float* hin, int K, int N, int layer) {
        // support = hin @ W
        dim3 grid((N_NODES + 127) / 128, N / 64);
        sgemm_kernel<<<grid, 256>>>(hin, W[layer], support, N_NODES, K, N);
        // agg = broadcast(bias)
        int total  = N_NODES * N;
        int total4 = total / 4;
        init_bias_kernel<<<(total4 + 255) / 256, 256>>>(
            (float4*)agg, (const float4*)b[layer], total4, N / 4 - 1);
        // agg += A_sparse @ support
        int nchunk = N / 4;
        long long nth = (long long)N_EDGES * nchunk;
        scatter_kernel<<<(int)((nth + 255) / 256), 256>>>(
            (const float4*)support, esrc, edst, ew, (float4*)agg,
            N_EDGES, nchunk);
    };

    auto epi = [&](float* out0, float* out_sum, const float* add1,
                   const float* add2, int N) {
        int total4 = N_NODES * N / 4;
        epilogue_kernel<<<(total4 + 255) / 256, 256>>>(
            (const float4*)agg, (float4*)out0, (float4*)out_sum,
            (const float4*)add1, (const float4*)add2, total4);
    };

    // L1: x(128) -> 64
    gconv(x, 128, 64, 0);
    epi(h, nullptr, nullptr, nullptr, 64);          // h = l1
    // L2: 64 -> 128
    gconv(h, 64, 128, 1);
    epi(h, nullptr, nullptr, nullptr, 128);         // h = l2
    // L3: 128 -> 256
    gconv(h, 128, 256, 2);
    epi(l3, nullptr, nullptr, nullptr, 256);        // l3
    // L4: l3 -> 256
    gconv(l3, 256, 256, 3);
    epi(l4, h, l3, nullptr, 256);                   // l4 ; h = l4 + l3
    // L5: (l4+l3) -> 256
    gconv(h, 256, 256, 4);
    epi(nullptr, h, l4, l3, 256);                   // h = l5 + l4 + l3
    // L6: (l5+l4+l3) -> 256
    gconv(h, 256, 256, 5);
    epi((float*)d_out, nullptr, nullptr, nullptr, 256);  // out = relu(...)
}

// round 3
// speedup vs baseline: 1.4096x; 1.4096x over previous
#include <cuda_runtime.h>
#include <cuda_bf16.h>
#include <cstdint>

#define N_NODES 50000
#define N_EDGES 300000
#define MAXF    256

// ---------------- scratch (device globals; no allocation allowed) ----------
__device__ float g_support[(size_t)N_NODES * MAXF];
__device__ float g_agg    [(size_t)N_NODES * MAXF];
__device__ float g_l3     [(size_t)N_NODES * MAXF];
__device__ float g_l4     [(size_t)N_NODES * MAXF];
// bf16 hi/lo planes for activations (GEMM A operand)
__device__ unsigned short g_ahi[(size_t)N_NODES * MAXF];
__device__ unsigned short g_alo[(size_t)N_NODES * MAXF];
// bf16 hi/lo planes for weights, flat-packed per layer
#define W_TOTAL 245760
__device__ unsigned short g_whi[W_TOTAL];
__device__ unsigned short g_wlo[W_TOTAL];

// =================== small helpers =========================================
__device__ __forceinline__ uint32_t smem_u32(const void* p) {
    uint32_t a;
    asm("{ .reg .u64 t; cvta.to.shared.u64 t, %1; cvt.u32.u64 %0, t; }"
        : "=r"(a) : "l"(p));
    return a;
}
__device__ __forceinline__ unsigned short f2bf(float x) {
    __nv_bfloat16 b = __float2bfloat16(x);
    return *(unsigned short*)&b;
}
__device__ __forceinline__ float bf2f(unsigned short u) {
    __nv_bfloat16 b = *(__nv_bfloat16*)&u;
    return __bfloat162float(b);
}
__device__ __forceinline__ void cp16(uint32_t dst, const void* src, bool valid) {
    int sz = valid ? 16 : 0;
    asm volatile("cp.async.cg.shared.global [%0], [%1], 16, %2;"
                 :: "r"(dst), "l"(src), "r"(sz));
}
__device__ __forceinline__ void ldsm4(uint32_t* r, uint32_t addr) {
    asm volatile("ldmatrix.sync.aligned.m8n8.x4.shared.b16 {%0,%1,%2,%3}, [%4];"
                 : "=r"(r[0]), "=r"(r[1]), "=r"(r[2]), "=r"(r[3]) : "r"(addr));
}
__device__ __forceinline__ void ldsm4t(uint32_t* r, uint32_t addr) {
    asm volatile("ldmatrix.sync.aligned.m8n8.x4.trans.shared.b16 {%0,%1,%2,%3}, [%4];"
                 : "=r"(r[0]), "=r"(r[1]), "=r"(r[2]), "=r"(r[3]) : "r"(addr));
}
__device__ __forceinline__ void mma_bf16(float* d, const uint32_t* a,
                                         uint32_t b0, uint32_t b1) {
    asm volatile(
        "mma.sync.aligned.m16n8k16.row.col.f32.bf16.bf16.f32 "
        "{%0,%1,%2,%3}, {%4,%5,%6,%7}, {%8,%9}, {%0,%1,%2,%3};"
        : "+f"(d[0]), "+f"(d[1]), "+f"(d[2]), "+f"(d[3])
        : "r"(a[0]), "r"(a[1]), "r"(a[2]), "r"(a[3]), "r"(b0), "r"(b1));
}

// ========== bf16x3 mma.sync GEMM: C[M,N] = A[M,K] @ W[K,N] =================
// A,W given as bf16 hi/lo planes. BM=128, BK=32, 8 warps, warp tile 32x(BN/2).
// Double-buffered cp.async pipeline. XOR-swizzled 16B chunks in smem.
template<int K, int BN>
__global__ __launch_bounds__(256, 1) void gemm_bf16x3_kernel(
    const unsigned short* __restrict__ Ahi, const unsigned short* __restrict__ Alo,
    const unsigned short* __restrict__ Whi, const unsigned short* __restrict__ Wlo,
    float* __restrict__ C, int M, int N)
{
    constexpr int NT   = K / 32;          // K tiles
    constexpr int BB   = 64 * BN;         // bytes per B plane (32 rows * BN*2B)
    constexpr int BUFB = 16384 + 2 * BB;  // A hi+lo (2*8KB) + B hi+lo
    constexpr int NTN  = BN / 16;         // n8-tiles per warp
    constexpr int NP   = NTN / 2;         // ldmatrix x4 pairs per warp
    constexpr int BC   = BN / 8;          // 16B chunks per B row

    extern __shared__ __align__(128) char smem[];
    const uint32_t sb = smem_u32(smem);

    const int tid  = threadIdx.x;
    const int lane = tid & 31;
    const int wid  = tid >> 5;
    const int m0   = blockIdx.x * 128;
    const int bn0  = blockIdx.y * BN;
    const int wm   = (wid & 3) * 32;
    const int wn   = (wid >> 2) * (BN / 2);

    float acc[2][NTN][4];
    #pragma unroll
    for (int i = 0; i < 2; i++)
        #pragma unroll
        for (int j = 0; j < NTN; j++)
            #pragma unroll
            for (int k = 0; k < 4; k++) acc[i][j][k] = 0.f;

    auto load_tile = [&](int t, int b) {
        const uint32_t base = sb + b * BUFB;
        const int kr0 = t * 32;
        // A planes: 128 rows x 4 chunks of 16B each
        #pragma unroll
        for (int i = tid; i < 512; i += 256) {
            int r = i >> 2, c = i & 3;
            int gr = m0 + r;
            uint32_t d = base + r * 64 + ((c ^ ((r >> 1) & 3)) << 4);
            size_t go = (size_t)gr * K + kr0 + c * 8;
            cp16(d,        Ahi + go, gr < M);
            cp16(d + 8192, Alo + go, gr < M);
        }
        // B planes: 32 rows x BC chunks
        #pragma unroll
        for (int i = tid; i < 32 * BC; i += 256) {
            int r = i / BC, c = i % BC;
            uint32_t d = base + 16384 + r * (BN * 2) + ((c ^ (r & 7)) << 4);
            size_t go = (size_t)(kr0 + r) * N + bn0 + c * 8;
            cp16(d,      Whi + go, true);
            cp16(d + BB, Wlo + go, true);
        }
        asm volatile("cp.async.commit_group;" ::: "memory");
    };

    auto compute = [&](int b) {
        const uint32_t base  = sb + b * BUFB;
        const uint32_t baseB = base + 16384;
        #pragma unroll
        for (int ks = 0; ks < 2; ks++) {
            uint32_t ah[2][4], al[2][4];
            int lrow = lane & 15;
            int lch  = 2 * ks + (lane >> 4);
            #pragma unroll
            for (int mt = 0; mt < 2; mt++) {
                int r = wm + mt * 16 + lrow;
                uint32_t addr = base + r * 64 + ((lch ^ ((r >> 1) & 3)) << 4);
                ldsm4(ah[mt], addr);
                ldsm4(al[mt], addr + 8192);
            }
            uint32_t bh[NP][4], bl[NP][4];
            int kr = ks * 16 + (lane & 15);
            #pragma unroll
            for (int np = 0; np < NP; np++) {
                int cb = (wn + np * 16 + (lane >> 4) * 8) >> 3;
                uint32_t addr = baseB + kr * (BN * 2) + ((cb ^ (kr & 7)) << 4);
                ldsm4t(bh[np], addr);
                ldsm4t(bl[np], addr + BB);
            }
            #pragma unroll
            for (int mt = 0; mt < 2; mt++)
                #pragma unroll
                for (int np = 0; np < NP; np++) {
                    mma_bf16(acc[mt][2*np],   ah[mt], bh[np][0], bh[np][1]);
                    mma_bf16(acc[mt][2*np],   ah[mt], bl[np][0], bl[np][1]);
                    mma_bf16(acc[mt][2*np],   al[mt], bh[np][0], bh[np][1]);
                    mma_bf16(acc[mt][2*np+1], ah[mt], bh[np][2], bh[np][3]);
                    mma_bf16(acc[mt][2*np+1], ah[mt], bl[np][2], bl[np][3]);
                    mma_bf16(acc[mt][2*np+1], al[mt], bh[np][2], bh[np][3]);
                }
        }
    };

    load_tile(0, 0);
    #pragma unroll 1
    for (int t = 0; t < NT; t++) {
        if (t + 1 < NT) {
            load_tile(t + 1, (t + 1) & 1);
            asm volatile("cp.async.wait_group 1;" ::: "memory");
        } else {
            asm volatile("cp.async.wait_group 0;" ::: "memory");
        }
        __syncthreads();
        compute(t & 1);
        __syncthreads();
    }

    // write out
    #pragma unroll
    for (int mt = 0; mt < 2; mt++)
        #pragma unroll
        for (int nt = 0; nt < NTN; nt++) {
            int row = m0 + wm + mt * 16 + (lane >> 2);
            int col = bn0 + wn + nt * 8 + (lane & 3) * 2;
            if (row < M)
                *(float2*)&C[(size_t)row * N + col] =
                    make_float2(acc[mt][nt][0], acc[mt][nt][1]);
            if (row + 8 < M)
                *(float2*)&C[(size_t)(row + 8) * N + col] =
                    make_float2(acc[mt][nt][2], acc[mt][nt][3]);
        }
}

// ---------------- split: fp32 -> bf16 hi/lo planes -------------------------
__global__ void split_kernel(const float4* __restrict__ in,
                             ushort4* __restrict__ hi, ushort4* __restrict__ lo,
                             int n4)
{
    int i = blockIdx.x * blockDim.x + threadIdx.x;
    if (i >= n4) return;
    float4 v = in[i];
    ushort4 h, l;
    h.x = f2bf(v.x); l.x = f2bf(v.x - bf2f(h.x));
    h.y = f2bf(v.y); l.y = f2bf(v.y - bf2f(h.y));
    h.z = f2bf(v.z); l.z = f2bf(v.z - bf2f(h.z));
    h.w = f2bf(v.w); l.w = f2bf(v.w - bf2f(h.w));
    hi[i] = h; lo[i] = l;
}

// ---------------- zero-fill ------------------------------------------------
__global__ void zero_kernel(float4* __restrict__ p, int n4)
{
    int i = blockIdx.x * blockDim.x + threadIdx.x;
    if (i < n4) p[i] = make_float4(0.f, 0.f, 0.f, 0.f);
}

// ---------------- scatter: agg[dst] += support[src] * w --------------------
__global__ void scatter_kernel(const float4* __restrict__ support,
                               const int*   __restrict__ src,
                               const int*   __restrict__ dst,
                               const float* __restrict__ w,
                               float4* __restrict__ agg,
                               int E, int nchunk)
{
    int idx = blockIdx.x * blockDim.x + threadIdx.x;
    int e = idx / nchunk;
    int c = idx - e * nchunk;
    if (e >= E) return;
    int   s  = __ldg(&src[e]);
    int   d  = __ldg(&dst[e]);
    float wt = __ldg(&w[e]);
    float4 v = __ldg(&support[(size_t)s * nchunk + c]);
    float4 m = make_float4(v.x * wt, v.y * wt, v.z * wt, v.w * wt);
    atomicAdd(&agg[(size_t)d * nchunk + c], m);
}

// ------- epilogue: r = relu(agg + bias); optional fp32 out, residual sums,
//         and bf16 hi/lo plane split of (r + add1 + add2) ------------------
__global__ void epilogue_kernel(const float4* __restrict__ agg,
                                const float4* __restrict__ bias, int maskN4,
                                float4* __restrict__ out_f32,
                                ushort4* __restrict__ hi, ushort4* __restrict__ lo,
                                const float4* __restrict__ add1,
                                const float4* __restrict__ add2,
                                int total4)
{
    int i = blockIdx.x * blockDim.x + threadIdx.x;
    if (i >= total4) return;
    float4 a = agg[i];
    float4 bb = bias[i & maskN4];
    float4 r = make_float4(fmaxf(a.x + bb.x, 0.f), fmaxf(a.y + bb.y, 0.f),
                           fmaxf(a.z + bb.z, 0.f), fmaxf(a.w + bb.w, 0.f));
    if (out_f32) out_f32[i] = r;
    if (hi) {
        float4 s = r;
        if (add1) {
            float4 s1 = add1[i];
            s.x += s1.x; s.y += s1.y; s.z += s1.z; s.w += s1.w;
        }
        if (add2) {
            float4 s2 = add2[i];
            s.x += s2.x; s.y += s2.y; s.z += s2.z; s.w += s2.w;
        }
        ushort4 h, l;
        h.x = f2bf(s.x); l.x = f2bf(s.x - bf2f(h.x));
        h.y = f2bf(s.y); l.y = f2bf(s.y - bf2f(h.y));
        h.z = f2bf(s.z); l.z = f2bf(s.z - bf2f(h.z));
        h.w = f2bf(s.w); l.w = f2bf(s.w - bf2f(h.w));
        hi[i] = h; lo[i] = l;
    }
}

// ---------------------------------------------------------------------------
extern "C" void kernel_launch(void* const* d_in, const int* in_sizes, int n_in,
                              void* d_out, int out_size)
{
    const float* x    = (const float*)d_in[0];
    const int*   esrc = (const int*)  d_in[1];
    const int*   edst = (const int*)  d_in[2];
    const float* ew   = (const float*)d_in[3];
    const float* W[6];
    const float* b[6];
    for (int i = 0; i < 6; i++) {
        W[i] = (const float*)d_in[4 + 2 * i];
        b[i] = (const float*)d_in[5 + 2 * i];
    }

    float *support, *agg, *l3, *l4;
    unsigned short *ahi, *alo, *whi, *wlo;
    cudaGetSymbolAddress((void**)&support, g_support);
    cudaGetSymbolAddress((void**)&agg,     g_agg);
    cudaGetSymbolAddress((void**)&l3,      g_l3);
    cudaGetSymbolAddress((void**)&l4,      g_l4);
    cudaGetSymbolAddress((void**)&ahi,     g_ahi);
    cudaGetSymbolAddress((void**)&alo,     g_alo);
    cudaGetSymbolAddress((void**)&whi,     g_whi);
    cudaGetSymbolAddress((void**)&wlo,     g_wlo);

    static const int wdim[6][2] = {{128,64},{64,128},{128,256},{256,256},{256,256},{256,256}};
    static const int woff[6]    = {0, 8192, 16384, 49152, 114688, 180224};

    cudaFuncSetAttribute(gemm_bf16x3_kernel<128, 64>,
        cudaFuncAttributeMaxDynamicSharedMemorySize, 49152);
    cudaFuncSetAttribute(gemm_bf16x3_kernel<64, 128>,
        cudaFuncAttributeMaxDynamicSharedMemorySize, 65536);
    cudaFuncSetAttribute(gemm_bf16x3_kernel<128, 128>,
        cudaFuncAttributeMaxDynamicSharedMemorySize, 65536);
    cudaFuncSetAttribute(gemm_bf16x3_kernel<256, 128>,
        cudaFuncAttributeMaxDynamicSharedMemorySize, 65536);

    // ---- weight + input splits -------------------------------------------
    for (int i = 0; i < 6; i++) {
        int n4 = wdim[i][0] * wdim[i][1] / 4;
        split_kernel<<<(n4 + 255) / 256, 256>>>(
            (const float4*)W[i], (ushort4*)(whi + woff[i]), (ushort4*)(wlo + woff[i]), n4);
    }
    {
        int n4 = N_NODES * 128 / 4;
        split_kernel<<<(n4 + 255) / 256, 256>>>(
            (const float4*)x, (ushort4*)ahi, (ushort4*)alo, n4);
    }

    const int GRID_M = (N_NODES + 127) / 128;   // 391

    auto sparse = [&](int N, int layer) {
        int total4 = N_NODES * N / 4;
        zero_kernel<<<(total4 + 255) / 256, 256>>>((float4*)agg, total4);
        int nchunk = N / 4;
        long long nth = (long long)N_EDGES * nchunk;
        scatter_kernel<<<(int)((nth + 255) / 256), 256>>>(
            (const float4*)support, esrc, edst, ew, (float4*)agg,
            N_EDGES, nchunk);
    };
    auto epi = [&](int layer, int N, float* out_f32, bool planes,
                   const float* add1, const float* add2) {
        int total4 = N_NODES * N / 4;
        epilogue_kernel<<<(total4 + 255) / 256, 256>>>(
            (const float4*)agg, (const float4*)b[layer], N / 4 - 1,
            (float4*)out_f32,
            planes ? (ushort4*)ahi : nullptr, planes ? (ushort4*)alo : nullptr,
            (const float4*)add1, (const float4*)add2, total4);
    };

    // L1: x(128) -> 64
    gemm_bf16x3_kernel<128, 64><<<dim3(GRID_M, 1), 256, 49152>>>(
        ahi, alo, whi + woff[0], wlo + woff[0], support, N_NODES, 64);
    sparse(64, 0);
    epi(0, 64, nullptr, true, nullptr, nullptr);            // planes = l1
    // L2: 64 -> 128
    gemm_bf16x3_kernel<64, 128><<<dim3(GRID_M, 1), 256, 65536>>>(
        ahi, alo, whi + woff[1], wlo + woff[1], support, N_NODES, 128);
    sparse(128, 1);
    epi(1, 128, nullptr, true, nullptr, nullptr);           // planes = l2
    // L3: 128 -> 256
    gemm_bf16x3_kernel<128, 128><<<dim3(GRID_M, 2), 256, 65536>>>(
        ahi, alo, whi + woff[2], wlo + woff[2], support, N_NODES, 256);
    sparse(256, 2);
    epi(2, 256, l3, true, nullptr, nullptr);                // l3 ; planes = l3
    // L4: l3 -> 256
    gemm_bf16x3_kernel<256, 128><<<dim3(GRID_M, 2), 256, 65536>>>(
        ahi, alo, whi + woff[3], wlo + woff[3], support, N_NODES, 256);
    sparse(256, 3);
    epi(3, 256, l4, true, l3, nullptr);                     // l4 ; planes = l4+l3
    // L5: (l4+l3) -> 256
    gemm_bf16x3_kernel<256, 128><<<dim3(GRID_M, 2), 256, 65536>>>(
        ahi, alo, whi + woff[4], wlo + woff[4], support, N_NODES, 256);
    sparse(256, 4);
    epi(4, 256, nullptr, true, l4, l3);                     // planes = l5+l4+l3
    // L6: (l5+l4+l3) -> 256
    gemm_bf16x3_kernel<256, 128><<<dim3(GRID_M, 2), 256, 65536>>>(
        ahi, alo, whi + woff[5], wlo + woff[5], support, N_NODES, 256);
    sparse(256, 5);
    epi(5, 256, (float*)d_out, false, nullptr, nullptr);    // out = relu(...)
}

// round 5
// speedup vs baseline: 2.3020x; 1.6331x over previous
#include <cuda_runtime.h>
#include <cuda_bf16.h>
#include <cstdint>

#define N_NODES 50000
#define N_EDGES 300000
#define MAXF    256

// ---------------- scratch (device globals; no allocation allowed) ----------
__device__ float g_support[(size_t)N_NODES * MAXF];
__device__ float g_l3     [(size_t)N_NODES * MAXF];
__device__ float g_l4     [(size_t)N_NODES * MAXF];
// bf16 hi/lo planes for activations (GEMM A operand)
__device__ unsigned short g_ahi[(size_t)N_NODES * MAXF];
__device__ unsigned short g_alo[(size_t)N_NODES * MAXF];
// bf16 hi/lo planes for weights, flat-packed per layer
#define W_TOTAL 245760
__device__ unsigned short g_whi[W_TOTAL];
__device__ unsigned short g_wlo[W_TOTAL];
// CSR-by-dst edge grouping (rebuilt every call)
__device__ int    g_counts[N_NODES];
__device__ int    g_start [N_NODES];
__device__ int    g_wp    [N_NODES];
__device__ int    g_cursor;
__device__ float2 g_ebuf  [N_EDGES];    // (src as int bits, weight)

// =================== small helpers =========================================
__device__ __forceinline__ uint32_t smem_u32(const void* p) {
    uint32_t a;
    asm("{ .reg .u64 t; cvta.to.shared.u64 t, %1; cvt.u32.u64 %0, t; }"
        : "=r"(a) : "l"(p));
    return a;
}
__device__ __forceinline__ unsigned short f2bf(float x) {
    __nv_bfloat16 b = __float2bfloat16(x);
    return *(unsigned short*)&b;
}
__device__ __forceinline__ float bf2f(unsigned short u) {
    __nv_bfloat16 b = *(__nv_bfloat16*)&u;
    return __bfloat162float(b);
}
__device__ __forceinline__ void cp16(uint32_t dst, const void* src, bool valid) {
    int sz = valid ? 16 : 0;
    asm volatile("cp.async.cg.shared.global [%0], [%1], 16, %2;"
                 :: "r"(dst), "l"(src), "r"(sz));
}
__device__ __forceinline__ void ldsm4(uint32_t* r, uint32_t addr) {
    asm volatile("ldmatrix.sync.aligned.m8n8.x4.shared.b16 {%0,%1,%2,%3}, [%4];"
                 : "=r"(r[0]), "=r"(r[1]), "=r"(r[2]), "=r"(r[3]) : "r"(addr));
}
__device__ __forceinline__ void ldsm4t(uint32_t* r, uint32_t addr) {
    asm volatile("ldmatrix.sync.aligned.m8n8.x4.trans.shared.b16 {%0,%1,%2,%3}, [%4];"
                 : "=r"(r[0]), "=r"(r[1]), "=r"(r[2]), "=r"(r[3]) : "r"(addr));
}
__device__ __forceinline__ void mma_bf16(float* d, const uint32_t* a,
                                         uint32_t b0, uint32_t b1) {
    asm volatile(
        "mma.sync.aligned.m16n8k16.row.col.f32.bf16.bf16.f32 "
        "{%0,%1,%2,%3}, {%4,%5,%6,%7}, {%8,%9}, {%0,%1,%2,%3};"
        : "+f"(d[0]), "+f"(d[1]), "+f"(d[2]), "+f"(d[3])
        : "r"(a[0]), "r"(a[1]), "r"(a[2]), "r"(a[3]), "r"(b0), "r"(b1));
}

// ========== bf16x3 mma.sync GEMM: C[M,N] = A[M,K] @ W[K,N] =================
template<int K, int BN>
__global__ __launch_bounds__(256, 1) void gemm_bf16x3_kernel(
    const unsigned short* __restrict__ Ahi, const unsigned short* __restrict__ Alo,
    const unsigned short* __restrict__ Whi, const unsigned short* __restrict__ Wlo,
    float* __restrict__ C, int M, int N)
{
    constexpr int NT   = K / 32;
    constexpr int BB   = 64 * BN;
    constexpr int BUFB = 16384 + 2 * BB;
    constexpr int NTN  = BN / 16;
    constexpr int NP   = NTN / 2;
    constexpr int BC   = BN / 8;

    extern __shared__ __align__(128) char smem[];
    const uint32_t sb = smem_u32(smem);

    const int tid  = threadIdx.x;
    const int lane = tid & 31;
    const int wid  = tid >> 5;
    const int m0   = blockIdx.x * 128;
    const int bn0  = blockIdx.y * BN;
    const int wm   = (wid & 3) * 32;
    const int wn   = (wid >> 2) * (BN / 2);

    float acc[2][NTN][4];
    #pragma unroll
    for (int i = 0; i < 2; i++)
        #pragma unroll
        for (int j = 0; j < NTN; j++)
            #pragma unroll
            for (int k = 0; k < 4; k++) acc[i][j][k] = 0.f;

    auto load_tile = [&](int t, int b) {
        const uint32_t base = sb + b * BUFB;
        const int kr0 = t * 32;
        #pragma unroll
        for (int i = tid; i < 512; i += 256) {
            int r = i >> 2, c = i & 3;
            int gr = m0 + r;
            uint32_t d = base + r * 64 + ((c ^ ((r >> 1) & 3)) << 4);
            size_t go = (size_t)gr * K + kr0 + c * 8;
            cp16(d,        Ahi + go, gr < M);
            cp16(d + 8192, Alo + go, gr < M);
        }
        #pragma unroll
        for (int i = tid; i < 32 * BC; i += 256) {
            int r = i / BC, c = i % BC;
            uint32_t d = base + 16384 + r * (BN * 2) + ((c ^ (r & 7)) << 4);
            size_t go = (size_t)(kr0 + r) * N + bn0 + c * 8;
            cp16(d,      Whi + go, true);
            cp16(d + BB, Wlo + go, true);
        }
        asm volatile("cp.async.commit_group;" ::: "memory");
    };

    auto compute = [&](int b) {
        const uint32_t base  = sb + b * BUFB;
        const uint32_t baseB = base + 16384;
        #pragma unroll
        for (int ks = 0; ks < 2; ks++) {
            uint32_t ah[2][4], al[2][4];
            int lrow = lane & 15;
            int lch  = 2 * ks + (lane >> 4);
            #pragma unroll
            for (int mt = 0; mt < 2; mt++) {
                int r = wm + mt * 16 + lrow;
                uint32_t addr = base + r * 64 + ((lch ^ ((r >> 1) & 3)) << 4);
                ldsm4(ah[mt], addr);
                ldsm4(al[mt], addr + 8192);
            }
            uint32_t bh[NP][4], bl[NP][4];
            int kr = ks * 16 + (lane & 15);
            #pragma unroll
            for (int np = 0; np < NP; np++) {
                int cb = (wn + np * 16 + (lane >> 4) * 8) >> 3;
                uint32_t addr = baseB + kr * (BN * 2) + ((cb ^ (kr & 7)) << 4);
                ldsm4t(bh[np], addr);
                ldsm4t(bl[np], addr + BB);
            }
            #pragma unroll
            for (int mt = 0; mt < 2; mt++)
                #pragma unroll
                for (int np = 0; np < NP; np++) {
                    mma_bf16(acc[mt][2*np],   ah[mt], bh[np][0], bh[np][1]);
                    mma_bf16(acc[mt][2*np],   ah[mt], bl[np][0], bl[np][1]);
                    mma_bf16(acc[mt][2*np],   al[mt], bh[np][0], bh[np][1]);
                    mma_bf16(acc[mt][2*np+1], ah[mt], bh[np][2], bh[np][3]);
                    mma_bf16(acc[mt][2*np+1], ah[mt], bl[np][2], bl[np][3]);
                    mma_bf16(acc[mt][2*np+1], al[mt], bh[np][2], bh[np][3]);
                }
        }
    };

    load_tile(0, 0);
    #pragma unroll 1
    for (int t = 0; t < NT; t++) {
        if (t + 1 < NT) {
            load_tile(t + 1, (t + 1) & 1);
            asm volatile("cp.async.wait_group 1;" ::: "memory");
        } else {
            asm volatile("cp.async.wait_group 0;" ::: "memory");
        }
        __syncthreads();
        compute(t & 1);
        __syncthreads();
    }

    #pragma unroll
    for (int mt = 0; mt < 2; mt++)
        #pragma unroll
        for (int nt = 0; nt < NTN; nt++) {
            int row = m0 + wm + mt * 16 + (lane >> 2);
            int col = bn0 + wn + nt * 8 + (lane & 3) * 2;
            if (row < M)
                *(float2*)&C[(size_t)row * N + col] =
                    make_float2(acc[mt][nt][0], acc[mt][nt][1]);
            if (row + 8 < M)
                *(float2*)&C[(size_t)(row + 8) * N + col] =
                    make_float2(acc[mt][nt][2], acc[mt][nt][3]);
        }
}

// ---------------- split: fp32 -> bf16 hi/lo planes -------------------------
__global__ void split_kernel(const float4* __restrict__ in,
                             ushort4* __restrict__ hi, ushort4* __restrict__ lo,
                             int n4)
{
    int i = blockIdx.x * blockDim.x + threadIdx.x;
    if (i >= n4) return;
    float4 v = in[i];
    ushort4 h, l;
    h.x = f2bf(v.x); l.x = f2bf(v.x - bf2f(h.x));
    h.y = f2bf(v.y); l.y = f2bf(v.y - bf2f(h.y));
    h.z = f2bf(v.z); l.z = f2bf(v.z - bf2f(h.z));
    h.w = f2bf(v.w); l.w = f2bf(v.w - bf2f(h.w));
    hi[i] = h; lo[i] = l;
}

// ---------------- CSR build (4 tiny kernels) -------------------------------
__global__ void csr_zero_kernel()
{
    int i = blockIdx.x * blockDim.x + threadIdx.x;
    if (i < N_NODES) g_counts[i] = 0;
    if (i == 0) g_cursor = 0;
}
__global__ void csr_hist_kernel(const int* __restrict__ dst)
{
    int e = blockIdx.x * blockDim.x + threadIdx.x;
    if (e < N_EDGES) atomicAdd(&g_counts[dst[e]], 1);
}
__global__ void csr_alloc_kernel()
{
    int i = blockIdx.x * blockDim.x + threadIdx.x;
    if (i < N_NODES) {
        int s = atomicAdd(&g_cursor, g_counts[i]);
        g_start[i] = s;
        g_wp[i]    = s;
    }
}
__global__ void csr_scatter_kernel(const int* __restrict__ src,
                                   const int* __restrict__ dst,
                                   const float* __restrict__ w)
{
    int e = blockIdx.x * blockDim.x + threadIdx.x;
    if (e >= N_EDGES) return;
    int pos = atomicAdd(&g_wp[dst[e]], 1);
    g_ebuf[pos] = make_float2(__int_as_float(src[e]), w[e]);
}

// ====== fused aggregation: warp per node ===================================
// out_row = relu( sum_e w_e * support[src_e] + bias )
// optional: out_f32 <- out_row ; planes <- split(out_row + add1 + add2)
template<int N>
__global__ __launch_bounds__(256) void agg_fused_kernel(
    const float* __restrict__ support,
    const float* __restrict__ bias,
    float* __restrict__ out_f32,
    ushort* __restrict__ hi, ushort* __restrict__ lo,
    const float* __restrict__ add1,
    const float* __restrict__ add2)
{
    int warp = (blockIdx.x * blockDim.x + threadIdx.x) >> 5;
    if (warp >= N_NODES) return;
    int lane = threadIdx.x & 31;
    int s   = __ldg(&g_start[warp]);
    int end = s + __ldg(&g_counts[warp]);

    constexpr int FPN = N / 32;    // 2, 4, or 8 floats per lane
    float acc[FPN];
    #pragma unroll
    for (int j = 0; j < FPN; j++) acc[j] = 0.f;

    #pragma unroll 1
    for (int e = s; e < end; e++) {
        float2 p = __ldg(&g_ebuf[e]);
        int   src = __float_as_int(p.x);
        float w   = p.y;
        const float* row = support + (size_t)src * N;
        if (FPN == 2) {
            float2 v = __ldg((const float2*)&row[lane * 2]);
            acc[0] += v.x * w; acc[1] += v.y * w;
        } else if (FPN == 4) {
            float4 v = __ldg((const float4*)&row[lane * 4]);
            acc[0] += v.x * w; acc[1] += v.y * w;
            acc[2] += v.z * w; acc[3] += v.w * w;
        } else {
            float4 v0 = __ldg((const float4*)&row[lane * 4]);
            float4 v1 = __ldg((const float4*)&row[128 + lane * 4]);
            acc[0] += v0.x * w; acc[1] += v0.y * w;
            acc[2] += v0.z * w; acc[3] += v0.w * w;
            acc[4] += v1.x * w; acc[5] += v1.y * w;
            acc[6] += v1.z * w; acc[7] += v1.w * w;
        }
    }

    int col0 = (FPN == 2) ? lane * 2 : lane * 4;
    size_t rowo = (size_t)warp * N;

    float r[FPN];
    #pragma unroll
    for (int j = 0; j < FPN; j++) {
        int col = (j < 4) ? col0 + j : 128 + col0 + (j - 4);
        r[j] = fmaxf(acc[j] + __ldg(&bias[col]), 0.f);
    }
    if (out_f32) {
        if (FPN == 2)
            *(float2*)&out_f32[rowo + col0] = make_float2(r[0], r[1]);
        else {
            *(float4*)&out_f32[rowo + col0] = make_float4(r[0], r[1], r[2], r[3]);
            if (FPN == 8)
                *(float4*)&out_f32[rowo + 128 + col0] = make_float4(r[4], r[5], r[6], r[7]);
        }
    }
    if (hi) {
        float sv[FPN];
        #pragma unroll
        for (int j = 0; j < FPN; j++) sv[j] = r[j];
        if (add1) {
            #pragma unroll
            for (int j = 0; j < FPN; j++) {
                int col = (j < 4) ? col0 + j : 128 + col0 + (j - 4);
                sv[j] += __ldg(&add1[rowo + col]);
            }
        }
        if (add2) {
            #pragma unroll
            for (int j = 0; j < FPN; j++) {
                int col = (j < 4) ? col0 + j : 128 + col0 + (j - 4);
                sv[j] += __ldg(&add2[rowo + col]);
            }
        }
        unsigned short hv[FPN], lv[FPN];
        #pragma unroll
        for (int j = 0; j < FPN; j++) {
            hv[j] = f2bf(sv[j]);
            lv[j] = f2bf(sv[j] - bf2f(hv[j]));
        }
        if (FPN == 2) {
            *(ushort2*)&hi[rowo + col0] = make_ushort2(hv[0], hv[1]);
            *(ushort2*)&lo[rowo + col0] = make_ushort2(lv[0], lv[1]);
        } else {
            *(ushort4*)&hi[rowo + col0] = make_ushort4(hv[0], hv[1], hv[2], hv[3]);
            *(ushort4*)&lo[rowo + col0] = make_ushort4(lv[0], lv[1], lv[2], lv[3]);
            if (FPN == 8) {
                *(ushort4*)&hi[rowo + 128 + col0] = make_ushort4(hv[4], hv[5], hv[6], hv[7]);
                *(ushort4*)&lo[rowo + 128 + col0] = make_ushort4(lv[4], lv[5], lv[6], lv[7]);
            }
        }
    }
}

// ---------------------------------------------------------------------------
extern "C" void kernel_launch(void* const* d_in, const int* in_sizes, int n_in,
                              void* d_out, int out_size)
{
    const float* x    = (const float*)d_in[0];
    const int*   esrc = (const int*)  d_in[1];
    const int*   edst = (const int*)  d_in[2];
    const float* ew   = (const float*)d_in[3];
    const float* W[6];
    const float* b[6];
    for (int i = 0; i < 6; i++) {
        W[i] = (const float*)d_in[4 + 2 * i];
        b[i] = (const float*)d_in[5 + 2 * i];
    }

    float *support, *l3, *l4;
    unsigned short *ahi, *alo, *whi, *wlo;
    cudaGetSymbolAddress((void**)&support, g_support);
    cudaGetSymbolAddress((void**)&l3,      g_l3);
    cudaGetSymbolAddress((void**)&l4,      g_l4);
    cudaGetSymbolAddress((void**)&ahi,     g_ahi);
    cudaGetSymbolAddress((void**)&alo,     g_alo);
    cudaGetSymbolAddress((void**)&whi,     g_whi);
    cudaGetSymbolAddress((void**)&wlo,     g_wlo);

    static const int wdim[6][2] = {{128,64},{64,128},{128,256},{256,256},{256,256},{256,256}};
    static const int woff[6]    = {0, 8192, 16384, 49152, 114688, 180224};

    cudaFuncSetAttribute(gemm_bf16x3_kernel<128, 64>,
        cudaFuncAttributeMaxDynamicSharedMemorySize, 49152);
    cudaFuncSetAttribute(gemm_bf16x3_kernel<64, 128>,
        cudaFuncAttributeMaxDynamicSharedMemorySize, 65536);
    cudaFuncSetAttribute(gemm_bf16x3_kernel<128, 128>,
        cudaFuncAttributeMaxDynamicSharedMemorySize, 65536);
    cudaFuncSetAttribute(gemm_bf16x3_kernel<256, 128>,
        cudaFuncAttributeMaxDynamicSharedMemorySize, 65536);

    // ---- weight + input splits -------------------------------------------
    for (int i = 0; i < 6; i++) {
        int n4 = wdim[i][0] * wdim[i][1] / 4;
        split_kernel<<<(n4 + 255) / 256, 256>>>(
            (const float4*)W[i], (ushort4*)(whi + woff[i]), (ushort4*)(wlo + woff[i]), n4);
    }
    {
        int n4 = N_NODES * 128 / 4;
        split_kernel<<<(n4 + 255) / 256, 256>>>(
            (const float4*)x, (ushort4*)ahi, (ushort4*)alo, n4);
    }

    // ---- CSR-by-dst build (once; edges shared by all 6 layers) -----------
    csr_zero_kernel<<<(N_NODES + 255) / 256, 256>>>();
    csr_hist_kernel<<<(N_EDGES + 255) / 256, 256>>>(edst);
    csr_alloc_kernel<<<(N_NODES + 255) / 256, 256>>>();
    csr_scatter_kernel<<<(N_EDGES + 255) / 256, 256>>>(esrc, edst, ew);

    const int GRID_M   = (N_NODES + 127) / 128;            // 391
    const int AGG_GRID = (N_NODES * 32 + 255) / 256;       // warp per node

    // L1: x(128) -> 64
    gemm_bf16x3_kernel<128, 64><<<dim3(GRID_M, 1), 256, 49152>>>(
        ahi, alo, whi + woff[0], wlo + woff[0], support, N_NODES, 64);
    agg_fused_kernel<64><<<AGG_GRID, 256>>>(
        support, b[0], nullptr, ahi, alo, nullptr, nullptr);       // planes = l1
    // L2: 64 -> 128
    gemm_bf16x3_kernel<64, 128><<<dim3(GRID_M, 1), 256, 65536>>>(
        ahi, alo, whi + woff[1], wlo + woff[1], support, N_NODES, 128);
    agg_fused_kernel<128><<<AGG_GRID, 256>>>(
        support, b[1], nullptr, ahi, alo, nullptr, nullptr);       // planes = l2
    // L3: 128 -> 256
    gemm_bf16x3_kernel<128, 128><<<dim3(GRID_M, 2), 256, 65536>>>(
        ahi, alo, whi + woff[2], wlo + woff[2], support, N_NODES, 256);
    agg_fused_kernel<256><<<AGG_GRID, 256>>>(
        support, b[2], l3, ahi, alo, nullptr, nullptr);            // l3 ; planes = l3
    // L4: l3 -> 256
    gemm_bf16x3_kernel<256, 128><<<dim3(GRID_M, 2), 256, 65536>>>(
        ahi, alo, whi + woff[3], wlo + woff[3], support, N_NODES, 256);
    agg_fused_kernel<256><<<AGG_GRID, 256>>>(
        support, b[3], l4, ahi, alo, l3, nullptr);                 // l4 ; planes = l4+l3
    // L5: (l4+l3) -> 256
    gemm_bf16x3_kernel<256, 128><<<dim3(GRID_M, 2), 256, 65536>>>(
        ahi, alo, whi + woff[4], wlo + woff[4], support, N_NODES, 256);
    agg_fused_kernel<256><<<AGG_GRID, 256>>>(
        support, b[4], nullptr, ahi, alo, l4, l3);                 // planes = l5+l4+l3
    // L6: (l5+l4+l3) -> 256
    gemm_bf16x3_kernel<256, 128><<<dim3(GRID_M, 2), 256, 65536>>>(
        ahi, alo, whi + woff[5], wlo + woff[5], support, N_NODES, 256);
    agg_fused_kernel<256><<<AGG_GRID, 256>>>(
        support, b[5], (float*)d_out, nullptr, nullptr, nullptr, nullptr);  // out
}

// round 6
// speedup vs baseline: 2.3981x; 1.0418x over previous
#include <cuda_runtime.h>
#include <cuda_bf16.h>
#include <cstdint>

#define N_NODES 50000
#define N_EDGES 300000
#define MAXF    256

// ---------------- scratch (device globals; no allocation allowed) ----------
__device__ float g_support[(size_t)N_NODES * MAXF];
__device__ float g_l3     [(size_t)N_NODES * MAXF];
__device__ float g_l4     [(size_t)N_NODES * MAXF];
// bf16 hi/lo planes for activations (GEMM A operand)
__device__ unsigned short g_ahi[(size_t)N_NODES * MAXF];
__device__ unsigned short g_alo[(size_t)N_NODES * MAXF];
// bf16 hi/lo planes for weights, flat-packed per layer
#define W_TOTAL 245760
__device__ unsigned short g_whi[W_TOTAL];
__device__ unsigned short g_wlo[W_TOTAL];
// CSR-by-dst edge grouping (rebuilt every call)
__device__ int    g_counts[N_NODES];
__device__ int    g_start [N_NODES];
__device__ int    g_wp    [N_NODES];
__device__ int    g_cursor;
__device__ float2 g_ebuf  [N_EDGES];    // (src as int bits, weight)

// =================== small helpers =========================================
__device__ __forceinline__ uint32_t smem_u32(const void* p) {
    uint32_t a;
    asm("{ .reg .u64 t; cvta.to.shared.u64 t, %1; cvt.u32.u64 %0, t; }"
        : "=r"(a) : "l"(p));
    return a;
}
__device__ __forceinline__ unsigned short f2bf(float x) {
    __nv_bfloat16 b = __float2bfloat16(x);
    return *(unsigned short*)&b;
}
__device__ __forceinline__ float bf2f(unsigned short u) {
    __nv_bfloat16 b = *(__nv_bfloat16*)&u;
    return __bfloat162float(b);
}
__device__ __forceinline__ void cp16(uint32_t dst, const void* src, bool valid) {
    int sz = valid ? 16 : 0;
    asm volatile("cp.async.cg.shared.global [%0], [%1], 16, %2;"
                 :: "r"(dst), "l"(src), "r"(sz));
}
__device__ __forceinline__ void ldsm4(uint32_t* r, uint32_t addr) {
    asm volatile("ldmatrix.sync.aligned.m8n8.x4.shared.b16 {%0,%1,%2,%3}, [%4];"
                 : "=r"(r[0]), "=r"(r[1]), "=r"(r[2]), "=r"(r[3]) : "r"(addr));
}
__device__ __forceinline__ void ldsm4t(uint32_t* r, uint32_t addr) {
    asm volatile("ldmatrix.sync.aligned.m8n8.x4.trans.shared.b16 {%0,%1,%2,%3}, [%4];"
                 : "=r"(r[0]), "=r"(r[1]), "=r"(r[2]), "=r"(r[3]) : "r"(addr));
}
__device__ __forceinline__ void mma_bf16(float* d, const uint32_t* a,
                                         uint32_t b0, uint32_t b1) {
    asm volatile(
        "mma.sync.aligned.m16n8k16.row.col.f32.bf16.bf16.f32 "
        "{%0,%1,%2,%3}, {%4,%5,%6,%7}, {%8,%9}, {%0,%1,%2,%3};"
        : "+f"(d[0]), "+f"(d[1]), "+f"(d[2]), "+f"(d[3])
        : "r"(a[0]), "r"(a[1]), "r"(a[2]), "r"(a[3]), "r"(b0), "r"(b1));
}

// ========== bf16x3 mma.sync GEMM: C[M,N] = A[M,K] @ W[K,N] =================
template<int K, int BN>
__global__ __launch_bounds__(256, 1) void gemm_bf16x3_kernel(
    const unsigned short* __restrict__ Ahi, const unsigned short* __restrict__ Alo,
    const unsigned short* __restrict__ Whi, const unsigned short* __restrict__ Wlo,
    float* __restrict__ C, int M, int N)
{
    constexpr int NT   = K / 32;
    constexpr int BB   = 64 * BN;
    constexpr int BUFB = 16384 + 2 * BB;
    constexpr int NTN  = BN / 16;
    constexpr int NP   = NTN / 2;
    constexpr int BC   = BN / 8;

    extern __shared__ __align__(128) char smem[];
    const uint32_t sb = smem_u32(smem);

    const int tid  = threadIdx.x;
    const int lane = tid & 31;
    const int wid  = tid >> 5;
    const int m0   = blockIdx.x * 128;
    const int bn0  = blockIdx.y * BN;
    const int wm   = (wid & 3) * 32;
    const int wn   = (wid >> 2) * (BN / 2);

    float acc[2][NTN][4];
    #pragma unroll
    for (int i = 0; i < 2; i++)
        #pragma unroll
        for (int j = 0; j < NTN; j++)
            #pragma unroll
            for (int k = 0; k < 4; k++) acc[i][j][k] = 0.f;

    auto load_tile = [&](int t, int b) {
        const uint32_t base = sb + b * BUFB;
        const int kr0 = t * 32;
        #pragma unroll
        for (int i = tid; i < 512; i += 256) {
            int r = i >> 2, c = i & 3;
            int gr = m0 + r;
            uint32_t d = base + r * 64 + ((c ^ ((r >> 1) & 3)) << 4);
            size_t go = (size_t)gr * K + kr0 + c * 8;
            cp16(d,        Ahi + go, gr < M);
            cp16(d + 8192, Alo + go, gr < M);
        }
        #pragma unroll
        for (int i = tid; i < 32 * BC; i += 256) {
            int r = i / BC, c = i % BC;
            uint32_t d = base + 16384 + r * (BN * 2) + ((c ^ (r & 7)) << 4);
            size_t go = (size_t)(kr0 + r) * N + bn0 + c * 8;
            cp16(d,      Whi + go, true);
            cp16(d + BB, Wlo + go, true);
        }
        asm volatile("cp.async.commit_group;" ::: "memory");
    };

    auto compute = [&](int b) {
        const uint32_t base  = sb + b * BUFB;
        const uint32_t baseB = base + 16384;
        #pragma unroll
        for (int ks = 0; ks < 2; ks++) {
            uint32_t ah[2][4], al[2][4];
            int lrow = lane & 15;
            int lch  = 2 * ks + (lane >> 4);
            #pragma unroll
            for (int mt = 0; mt < 2; mt++) {
                int r = wm + mt * 16 + lrow;
                uint32_t addr = base + r * 64 + ((lch ^ ((r >> 1) & 3)) << 4);
                ldsm4(ah[mt], addr);
                ldsm4(al[mt], addr + 8192);
            }
            uint32_t bh[NP][4], bl[NP][4];
            int kr = ks * 16 + (lane & 15);
            #pragma unroll
            for (int np = 0; np < NP; np++) {
                int cb = (wn + np * 16 + (lane >> 4) * 8) >> 3;
                uint32_t addr = baseB + kr * (BN * 2) + ((cb ^ (kr & 7)) << 4);
                ldsm4t(bh[np], addr);
                ldsm4t(bl[np], addr + BB);
            }
            #pragma unroll
            for (int mt = 0; mt < 2; mt++)
                #pragma unroll
                for (int np = 0; np < NP; np++) {
                    mma_bf16(acc[mt][2*np],   ah[mt], bh[np][0], bh[np][1]);
                    mma_bf16(acc[mt][2*np],   ah[mt], bl[np][0], bl[np][1]);
                    mma_bf16(acc[mt][2*np],   al[mt], bh[np][0], bh[np][1]);
                    mma_bf16(acc[mt][2*np+1], ah[mt], bh[np][2], bh[np][3]);
                    mma_bf16(acc[mt][2*np+1], ah[mt], bl[np][2], bl[np][3]);
                    mma_bf16(acc[mt][2*np+1], al[mt], bh[np][2], bh[np][3]);
                }
        }
    };

    load_tile(0, 0);
    #pragma unroll 1
    for (int t = 0; t < NT; t++) {
        if (t + 1 < NT) {
            load_tile(t + 1, (t + 1) & 1);
            asm volatile("cp.async.wait_group 1;" ::: "memory");
        } else {
            asm volatile("cp.async.wait_group 0;" ::: "memory");
        }
        __syncthreads();
        compute(t & 1);
        __syncthreads();
    }

    #pragma unroll
    for (int mt = 0; mt < 2; mt++)
        #pragma unroll
        for (int nt = 0; nt < NTN; nt++) {
            int row = m0 + wm + mt * 16 + (lane >> 2);
            int col = bn0 + wn + nt * 8 + (lane & 3) * 2;
            if (row < M)
                *(float2*)&C[(size_t)row * N + col] =
                    make_float2(acc[mt][nt][0], acc[mt][nt][1]);
            if (row + 8 < M)
                *(float2*)&C[(size_t)(row + 8) * N + col] =
                    make_float2(acc[mt][nt][2], acc[mt][nt][3]);
        }
}

// ---------------- batched split: weights (6 segs) + x in ONE launch --------
struct SplitArgs {
    const float4* w[6];     // weight tensors
    const float4* x;        // input features
};
#define WSEG_BLOCKS 240     // 61440 float4s of weights / 256
#define XSEG_N4     1600000 // 50000*128/4

__global__ void split_all_kernel(SplitArgs a,
                                 ushort4* __restrict__ whi4, ushort4* __restrict__ wlo4,
                                 ushort4* __restrict__ ahi4, ushort4* __restrict__ alo4)
{
    int bid = blockIdx.x;
    float4 v;
    ushort4* dh;
    ushort4* dl;
    int oi;
    if (bid < WSEG_BLOCKS) {
        int i = bid * 256 + threadIdx.x;          // [0, 61440)
        int seg = (i >= 2048) + (i >= 4096) + (i >= 12288) + (i >= 28672) + (i >= 45056);
        static const int off[6] = {0, 2048, 4096, 12288, 28672, 45056};
        v = __ldg(&a.w[seg][i - off[seg]]);
        dh = whi4; dl = wlo4; oi = i;
    } else {
        int i = (bid - WSEG_BLOCKS) * 256 + threadIdx.x;
        if (i >= XSEG_N4) return;
        v = __ldg(&a.x[i]);
        dh = ahi4; dl = alo4; oi = i;
    }
    ushort4 h, l;
    h.x = f2bf(v.x); l.x = f2bf(v.x - bf2f(h.x));
    h.y = f2bf(v.y); l.y = f2bf(v.y - bf2f(h.y));
    h.z = f2bf(v.z); l.z = f2bf(v.z - bf2f(h.z));
    h.w = f2bf(v.w); l.w = f2bf(v.w - bf2f(h.w));
    dh[oi] = h; dl[oi] = l;
}

// ---------------- CSR build (4 tiny kernels) -------------------------------
__global__ void csr_zero_kernel()
{
    int i = blockIdx.x * blockDim.x + threadIdx.x;
    if (i < N_NODES) g_counts[i] = 0;
    if (i == 0) g_cursor = 0;
}
__global__ void csr_hist_kernel(const int* __restrict__ dst)
{
    int e = blockIdx.x * blockDim.x + threadIdx.x;
    if (e < N_EDGES) atomicAdd(&g_counts[dst[e]], 1);
}
__global__ void csr_alloc_kernel()
{
    int i = blockIdx.x * blockDim.x + threadIdx.x;
    if (i < N_NODES) {
        int s = atomicAdd(&g_cursor, g_counts[i]);
        g_start[i] = s;
        g_wp[i]    = s;
    }
}
__global__ void csr_scatter_kernel(const int* __restrict__ src,
                                   const int* __restrict__ dst,
                                   const float* __restrict__ w)
{
    int e = blockIdx.x * blockDim.x + threadIdx.x;
    if (e >= N_EDGES) return;
    int pos = atomicAdd(&g_wp[dst[e]], 1);
    g_ebuf[pos] = make_float2(__int_as_float(src[e]), w[e]);
}

// ====== fused aggregation: warp per node, 2-edge MLP ======================
// out_row = relu( sum_e w_e * support[src_e] + bias )
// optional: out_f32 <- out_row ; planes <- split(out_row + add1 + add2)
template<int N>
__global__ __launch_bounds__(256) void agg_fused_kernel(
    const float* __restrict__ support,
    const float* __restrict__ bias,
    float* __restrict__ out_f32,
    ushort* __restrict__ hi, ushort* __restrict__ lo,
    const float* __restrict__ add1,
    const float* __restrict__ add2)
{
    int warp = (blockIdx.x * blockDim.x + threadIdx.x) >> 5;
    if (warp >= N_NODES) return;
    int lane = threadIdx.x & 31;
    int s   = __ldg(&g_start[warp]);
    int end = s + __ldg(&g_counts[warp]);

    constexpr int FPN = N / 32;    // 2, 4, or 8 floats per lane
    float acc[FPN];
    #pragma unroll
    for (int j = 0; j < FPN; j++) acc[j] = 0.f;

    auto gather1 = [&](float2 p) {
        int   src = __float_as_int(p.x);
        float w   = p.y;
        const float* row = support + (size_t)src * N;
        if (FPN == 2) {
            float2 v = __ldg((const float2*)&row[lane * 2]);
            acc[0] += v.x * w; acc[1] += v.y * w;
        } else if (FPN == 4) {
            float4 v = __ldg((const float4*)&row[lane * 4]);
            acc[0] += v.x * w; acc[1] += v.y * w;
            acc[2] += v.z * w; acc[3] += v.w * w;
        } else {
            float4 v0 = __ldg((const float4*)&row[lane * 4]);
            float4 v1 = __ldg((const float4*)&row[128 + lane * 4]);
            acc[0] += v0.x * w; acc[1] += v0.y * w;
            acc[2] += v0.z * w; acc[3] += v0.w * w;
            acc[4] += v1.x * w; acc[5] += v1.y * w;
            acc[6] += v1.z * w; acc[7] += v1.w * w;
        }
    };

    int e = s;
    #pragma unroll 1
    for (; e + 1 < end; e += 2) {
        // both edge records first, then two independent row gathers -> MLP 2
        float2 p0 = __ldg(&g_ebuf[e]);
        float2 p1 = __ldg(&g_ebuf[e + 1]);
        gather1(p0);
        gather1(p1);
    }
    if (e < end) gather1(__ldg(&g_ebuf[e]));

    int col0 = (FPN == 2) ? lane * 2 : lane * 4;
    size_t rowo = (size_t)warp * N;

    float r[FPN];
    #pragma unroll
    for (int j = 0; j < FPN; j++) {
        int col = (j < 4) ? col0 + j : 128 + col0 + (j - 4);
        r[j] = fmaxf(acc[j] + __ldg(&bias[col]), 0.f);
    }
    if (out_f32) {
        if (FPN == 2)
            *(float2*)&out_f32[rowo + col0] = make_float2(r[0], r[1]);
        else {
            *(float4*)&out_f32[rowo + col0] = make_float4(r[0], r[1], r[2], r[3]);
            if (FPN == 8)
                *(float4*)&out_f32[rowo + 128 + col0] = make_float4(r[4], r[5], r[6], r[7]);
        }
    }
    if (hi) {
        float sv[FPN];
        #pragma unroll
        for (int j = 0; j < FPN; j++) sv[j] = r[j];
        if (add1) {
            #pragma unroll
            for (int j = 0; j < FPN; j++) {
                int col = (j < 4) ? col0 + j : 128 + col0 + (j - 4);
                sv[j] += __ldg(&add1[rowo + col]);
            }
        }
        if (add2) {
            #pragma unroll
            for (int j = 0; j < FPN; j++) {
                int col = (j < 4) ? col0 + j : 128 + col0 + (j - 4);
                sv[j] += __ldg(&add2[rowo + col]);
            }
        }
        unsigned short hv[FPN], lv[FPN];
        #pragma unroll
        for (int j = 0; j < FPN; j++) {
            hv[j] = f2bf(sv[j]);
            lv[j] = f2bf(sv[j] - bf2f(hv[j]));
        }
        if (FPN == 2) {
            *(ushort2*)&hi[rowo + col0] = make_ushort2(hv[0], hv[1]);
            *(ushort2*)&lo[rowo + col0] = make_ushort2(lv[0], lv[1]);
        } else {
            *(ushort4*)&hi[rowo + col0] = make_ushort4(hv[0], hv[1], hv[2], hv[3]);
            *(ushort4*)&lo[rowo + col0] = make_ushort4(lv[0], lv[1], lv[2], lv[3]);
            if (FPN == 8) {
                *(ushort4*)&hi[rowo + 128 + col0] = make_ushort4(hv[4], hv[5], hv[6], hv[7]);
                *(ushort4*)&lo[rowo + 128 + col0] = make_ushort4(lv[4], lv[5], lv[6], lv[7]);
            }
        }
    }
}

// ---------------------------------------------------------------------------
extern "C" void kernel_launch(void* const* d_in, const int* in_sizes, int n_in,
                              void* d_out, int out_size)
{
    const float* x    = (const float*)d_in[0];
    const int*   esrc = (const int*)  d_in[1];
    const int*   edst = (const int*)  d_in[2];
    const float* ew   = (const float*)d_in[3];
    const float* W[6];
    const float* b[6];
    for (int i = 0; i < 6; i++) {
        W[i] = (const float*)d_in[4 + 2 * i];
        b[i] = (const float*)d_in[5 + 2 * i];
    }

    float *support, *l3, *l4;
    unsigned short *ahi, *alo, *whi, *wlo;
    cudaGetSymbolAddress((void**)&support, g_support);
    cudaGetSymbolAddress((void**)&l3,      g_l3);
    cudaGetSymbolAddress((void**)&l4,      g_l4);
    cudaGetSymbolAddress((void**)&ahi,     g_ahi);
    cudaGetSymbolAddress((void**)&alo,     g_alo);
    cudaGetSymbolAddress((void**)&whi,     g_whi);
    cudaGetSymbolAddress((void**)&wlo,     g_wlo);

    static const int woff[6] = {0, 8192, 16384, 49152, 114688, 180224};

    cudaFuncSetAttribute(gemm_bf16x3_kernel<128, 64>,
        cudaFuncAttributeMaxDynamicSharedMemorySize, 49152);
    cudaFuncSetAttribute(gemm_bf16x3_kernel<64, 128>,
        cudaFuncAttributeMaxDynamicSharedMemorySize, 65536);
    cudaFuncSetAttribute(gemm_bf16x3_kernel<128, 128>,
        cudaFuncAttributeMaxDynamicSharedMemorySize, 65536);
    cudaFuncSetAttribute(gemm_bf16x3_kernel<256, 128>,
        cudaFuncAttributeMaxDynamicSharedMemorySize, 65536);

    // ---- CSR-by-dst build first (launches 1-4) ---------------------------
    csr_zero_kernel<<<(N_NODES + 255) / 256, 256>>>();
    csr_hist_kernel<<<(N_EDGES + 255) / 256, 256>>>(edst);
    csr_alloc_kernel<<<(N_NODES + 255) / 256, 256>>>();
    csr_scatter_kernel<<<(N_EDGES + 255) / 256, 256>>>(esrc, edst, ew);

    // ---- all splits in one launch (launch 5) -----------------------------
    {
        SplitArgs a;
        for (int i = 0; i < 6; i++) a.w[i] = (const float4*)W[i];
        a.x = (const float4*)x;
        int grid = WSEG_BLOCKS + (XSEG_N4 + 255) / 256;
        split_all_kernel<<<grid, 256>>>(a, (ushort4*)whi, (ushort4*)wlo,
                                        (ushort4*)ahi, (ushort4*)alo);
    }

    const int GRID_M   = (N_NODES + 127) / 128;            // 391
    const int AGG_GRID = (N_NODES * 32 + 255) / 256;       // warp per node

    // L1: x(128) -> 64   (launch 6 — ncu -s 5 -c 1 captures this)
    gemm_bf16x3_kernel<128, 64><<<dim3(GRID_M, 1), 256, 49152>>>(
        ahi, alo, whi + woff[0], wlo + woff[0], support, N_NODES, 64);
    agg_fused_kernel<64><<<AGG_GRID, 256>>>(
        support, b[0], nullptr, ahi, alo, nullptr, nullptr);       // planes = l1
    // L2: 64 -> 128
    gemm_bf16x3_kernel<64, 128><<<dim3(GRID_M, 1), 256, 65536>>>(
        ahi, alo, whi + woff[1], wlo + woff[1], support, N_NODES, 128);
    agg_fused_kernel<128><<<AGG_GRID, 256>>>(
        support, b[1], nullptr, ahi, alo, nullptr, nullptr);       // planes = l2
    // L3: 128 -> 256
    gemm_bf16x3_kernel<128, 128><<<dim3(GRID_M, 2), 256, 65536>>>(
        ahi, alo, whi + woff[2], wlo + woff[2], support, N_NODES, 256);
    agg_fused_kernel<256><<<AGG_GRID, 256>>>(
        support, b[2], l3, ahi, alo, nullptr, nullptr);            // l3 ; planes = l3
    // L4: l3 -> 256
    gemm_bf16x3_kernel<256, 128><<<dim3(GRID_M, 2), 256, 65536>>>(
        ahi, alo, whi + woff[3], wlo + woff[3], support, N_NODES, 256);
    agg_fused_kernel<256><<<AGG_GRID, 256>>>(
        support, b[3], l4, ahi, alo, l3, nullptr);                 // l4 ; planes = l4+l3
    // L5: (l4+l3) -> 256
    gemm_bf16x3_kernel<256, 128><<<dim3(GRID_M, 2), 256, 65536>>>(
        ahi, alo, whi + woff[4], wlo + woff[4], support, N_NODES, 256);
    agg_fused_kernel<256><<<AGG_GRID, 256>>>(
        support, b[4], nullptr, ahi, alo, l4, l3);                 // planes = l5+l4+l3
    // L6: (l5+l4+l3) -> 256
    gemm_bf16x3_kernel<256, 128><<<dim3(GRID_M, 2), 256, 65536>>>(
        ahi, alo, whi + woff[5], wlo + woff[5], support, N_NODES, 256);
    agg_fused_kernel<256><<<AGG_GRID, 256>>>(
        support, b[5], (float*)d_out, nullptr, nullptr, nullptr, nullptr);  // out
}